// round 3
// baseline (speedup 1.0000x reference)
#include <cuda_runtime.h>
#include <math.h>

// Scratch: projected inputs xz (512 cols, biases folded) and xh (256 cols),
// laid out as [t][b][768] so each recurrence step reads a contiguous slab.
// Static __device__ array: allowed (no runtime allocation).
__device__ float g_xzh[131072 * 768];  // 402 MB zero-init bss

// ---------------------------------------------------------------------------
// Kernel 1: projection GEMM.  C[b*1024+t, 0:768] = x_row @ [W_zr | W_h] + bias
// 128x128 tile, BK=16, 256 threads, 8x8 microtile. N=768 -> 6 col tiles; each
// col tile lies entirely inside W_zr (cols<512) or W_h, so no inner branching.
// ---------------------------------------------------------------------------
__global__ __launch_bounds__(256, 2) void proj_gemm(
    const float* __restrict__ x,
    const float* __restrict__ Wzr,
    const float* __restrict__ Wh,
    const float* __restrict__ bzr,
    const float* __restrict__ bh)
{
    __shared__ float As[128][16];
    __shared__ float Bs[16][128];

    const int tid = threadIdx.x;
    const int tm = tid >> 4;          // 0..15
    const int tn = tid & 15;          // 0..15
    const int Mbase = blockIdx.y * 128;
    const int Nbase = blockIdx.x * 128;

    const bool isZr = (Nbase < 512);
    const float* __restrict__ W = isZr ? Wzr : Wh;
    const int ldw  = isZr ? 512 : 256;
    const int wcol = isZr ? Nbase : (Nbase - 512);

    float acc[8][8];
    #pragma unroll
    for (int i = 0; i < 8; i++)
        #pragma unroll
        for (int jj = 0; jj < 8; jj++) acc[i][jj] = 0.f;

    const int ra = tid >> 2;          // 0..63
    const int ka = (tid & 3) << 2;    // 0,4,8,12
    const int rb = tid >> 5;          // 0..7
    const int nb = (tid & 31) << 2;   // 0..124

    for (int kt = 0; kt < 256; kt += 16) {
        float4 a0 = *(const float4*)&x[(size_t)(Mbase + ra)      * 256 + kt + ka];
        float4 a1 = *(const float4*)&x[(size_t)(Mbase + ra + 64) * 256 + kt + ka];
        float4 w0 = *(const float4*)&W[(size_t)(kt + rb)     * ldw + wcol + nb];
        float4 w1 = *(const float4*)&W[(size_t)(kt + rb + 8) * ldw + wcol + nb];
        __syncthreads();
        *(float4*)&As[ra][ka]      = a0;
        *(float4*)&As[ra + 64][ka] = a1;
        *(float4*)&Bs[rb][nb]      = w0;
        *(float4*)&Bs[rb + 8][nb]  = w1;
        __syncthreads();
        #pragma unroll
        for (int kk = 0; kk < 16; kk++) {
            float a[8], b[8];
            #pragma unroll
            for (int i = 0; i < 8; i++) a[i] = As[tm * 8 + i][kk];
            *(float4*)&b[0] = *(const float4*)&Bs[kk][tn * 8];
            *(float4*)&b[4] = *(const float4*)&Bs[kk][tn * 8 + 4];
            #pragma unroll
            for (int i = 0; i < 8; i++)
                #pragma unroll
                for (int jj = 0; jj < 8; jj++)
                    acc[i][jj] += a[i] * b[jj];
        }
    }

    // bias folded here so the recurrence never touches it
    float bias[8];
    #pragma unroll
    for (int jj = 0; jj < 8; jj++) {
        int c = Nbase + tn * 8 + jj;
        bias[jj] = (c < 512) ? bzr[c] : bh[c - 512];
    }

    #pragma unroll
    for (int i = 0; i < 8; i++) {
        int r = Mbase + tm * 8 + i;   // r = b*1024 + t
        int b = r >> 10;
        int t = r & 1023;
        float* dst = &g_xzh[(size_t)((t << 7) + b) * 768 + Nbase + tn * 8];
        float4 v0, v1;
        v0.x = acc[i][0] + bias[0]; v0.y = acc[i][1] + bias[1];
        v0.z = acc[i][2] + bias[2]; v0.w = acc[i][3] + bias[3];
        v1.x = acc[i][4] + bias[4]; v1.y = acc[i][5] + bias[5];
        v1.z = acc[i][6] + bias[6]; v1.w = acc[i][7] + bias[7];
        *(float4*)dst       = v0;
        *(float4*)(dst + 4) = v1;
    }
}

// ---------------------------------------------------------------------------
// Kernel 2: recurrence. One block per 2 batch rows (64 blocks, 256 threads).
// Batch rows are fully independent -> no inter-block sync ever needed.
// Weights (768 KB) stream from L2 every step. Thread j owns z-columns
// (2j, 2j+1) in phase 1 and S-column j in phase 2.
// ---------------------------------------------------------------------------
__device__ __forceinline__ float sigm(float v) { return 1.f / (1.f + expf(-v)); }

__global__ __launch_bounds__(256, 1) void gru_recur(
    const float* __restrict__ Uzr,
    const float* __restrict__ Uh,
    float* __restrict__ out)
{
    __shared__ float2 h_sh[256];   // (h[b0][k], h[b1][k])
    __shared__ float2 rh_sh[256];  // (R*h) for both rows
    __shared__ float2 z_sh[256];   // update gate Z per column

    const int j  = threadIdx.x;
    const int b0 = blockIdx.x * 2;
    const float2* __restrict__ Uzr2 = (const float2*)Uzr;

    h_sh[j] = make_float2(0.f, 0.f);
    __syncthreads();

    for (int t = 0; t < 1024; t++) {
        const float* row0 = g_xzh + (size_t)((t << 7) + b0) * 768;
        const float* row1 = row0 + 768;
        // issue the input loads early; consumed after the matvec loops
        float2 xz0 = *(const float2*)(row0 + 2 * j);
        float2 xz1 = *(const float2*)(row1 + 2 * j);
        float  xh0 = row0[512 + j];
        float  xh1 = row1[512 + j];

        // ---- phase 1: z[:, 2j..2j+1] = xz + h @ U_zr ----
        float a00 = 0.f, a01 = 0.f, a10 = 0.f, a11 = 0.f;
        float2 ub[8];
        #pragma unroll
        for (int i = 0; i < 8; i++) ub[i] = Uzr2[i * 256 + j];
        #pragma unroll 1
        for (int k0 = 0; k0 < 248; k0 += 8) {
            float2 un[8];
            #pragma unroll
            for (int i = 0; i < 8; i++) un[i] = Uzr2[(k0 + 8 + i) * 256 + j];
            #pragma unroll
            for (int i = 0; i < 8; i++) {
                float2 hk = h_sh[k0 + i];
                a00 += hk.x * ub[i].x; a01 += hk.x * ub[i].y;
                a10 += hk.y * ub[i].x; a11 += hk.y * ub[i].y;
            }
            #pragma unroll
            for (int i = 0; i < 8; i++) ub[i] = un[i];
        }
        #pragma unroll
        for (int i = 0; i < 8; i++) {
            float2 hk = h_sh[248 + i];
            a00 += hk.x * ub[i].x; a01 += hk.x * ub[i].y;
            a10 += hk.y * ub[i].x; a11 += hk.y * ub[i].y;
        }
        a00 += xz0.x; a01 += xz0.y; a10 += xz1.x; a11 += xz1.y;

        float g00 = sigm(a00), g01 = sigm(a01);
        float g10 = sigm(a10), g11 = sigm(a11);
        if (j < 128) {
            // update gate Z, cols 2j, 2j+1
            z_sh[2 * j]     = make_float2(g00, g10);
            z_sh[2 * j + 1] = make_float2(g01, g11);
        } else {
            // reset gate R for hidden cols 2(j-128), +1 ; store R*h
            int c = 2 * (j - 128);
            float2 hc0 = h_sh[c], hc1 = h_sh[c + 1];
            rh_sh[c]     = make_float2(g00 * hc0.x, g10 * hc0.y);
            rh_sh[c + 1] = make_float2(g01 * hc1.x, g11 * hc1.y);
        }
        __syncthreads();

        // ---- phase 2: S[:, j] = tanh(xh + (R*h) @ U_h) ----
        float s0 = 0.f, s1 = 0.f;
        float ub2[8];
        #pragma unroll
        for (int i = 0; i < 8; i++) ub2[i] = Uh[i * 256 + j];
        #pragma unroll 1
        for (int k0 = 0; k0 < 248; k0 += 8) {
            float un2[8];
            #pragma unroll
            for (int i = 0; i < 8; i++) un2[i] = Uh[(k0 + 8 + i) * 256 + j];
            #pragma unroll
            for (int i = 0; i < 8; i++) {
                float2 rk = rh_sh[k0 + i];
                s0 += rk.x * ub2[i]; s1 += rk.y * ub2[i];
            }
            #pragma unroll
            for (int i = 0; i < 8; i++) ub2[i] = un2[i];
        }
        #pragma unroll
        for (int i = 0; i < 8; i++) {
            float2 rk = rh_sh[248 + i];
            s0 += rk.x * ub2[i]; s1 += rk.y * ub2[i];
        }
        s0 = tanhf(s0 + xh0);
        s1 = tanhf(s1 + xh1);

        float2 Z    = z_sh[j];
        float2 hold = h_sh[j];
        float hn0 = fmaf(Z.x, s0 - hold.x, hold.x);  // (1-Z)h + Z*S
        float hn1 = fmaf(Z.y, s1 - hold.y, hold.y);
        __syncthreads();           // all reads of h_sh/rh_sh complete
        h_sh[j] = make_float2(hn0, hn1);
        __syncthreads();           // h update visible for next step
    }

    float2 hf = h_sh[j];
    out[b0 * 256 + j]       = hf.x;
    out[(b0 + 1) * 256 + j] = hf.y;
}

// ---------------------------------------------------------------------------
extern "C" void kernel_launch(void* const* d_in, const int* in_sizes, int n_in,
                              void* d_out, int out_size)
{
    (void)in_sizes; (void)n_in; (void)out_size;
    const float* x   = (const float*)d_in[0];
    const float* Wzr = (const float*)d_in[1];
    const float* Uzr = (const float*)d_in[2];
    const float* bzr = (const float*)d_in[3];
    const float* Wh  = (const float*)d_in[4];
    const float* Uh  = (const float*)d_in[5];
    const float* bh  = (const float*)d_in[6];

    dim3 ggrid(6, 1024);                    // 768/128 x 131072/128
    proj_gemm<<<ggrid, 256>>>(x, Wzr, Wh, bzr, bh);
    gru_recur<<<64, 256>>>(Uzr, Uh, (float*)d_out);
}

// round 4
// speedup vs baseline: 3.9623x; 3.9623x over previous
#include <cuda_runtime.h>
#include <math.h>
#include <stdint.h>

typedef unsigned long long ull;

// Scratch: projected inputs [t][b][768] (xz cols 0..511 incl. bias, xh cols 512..767)
__device__ float g_xzh[131072 * 768];  // 402 MB static scratch

// ---------------------------------------------------------------------------
// helpers: packed f32x2 math, DSMEM, cluster sync
// ---------------------------------------------------------------------------
__device__ __forceinline__ ull dup2f(float x) {
    ull r; asm("mov.b64 %0, {%1, %1};" : "=l"(r) : "f"(x)); return r;
}
__device__ __forceinline__ void ffma2(ull& d, ull a, ull b) {
    asm("fma.rn.f32x2 %0, %1, %2, %0;" : "+l"(d) : "l"(a), "l"(b));
}
__device__ __forceinline__ void unpack2(ull v, float& x, float& y) {
    asm("mov.b64 {%0, %1}, %2;" : "=f"(x), "=f"(y) : "l"(v));
}
__device__ __forceinline__ uint32_t smem_u32(const void* p) {
    return (uint32_t)__cvta_generic_to_shared(p);
}
__device__ __forceinline__ uint32_t mapa_rank(uint32_t addr, uint32_t rank) {
    uint32_t r; asm("mapa.shared::cluster.u32 %0, %1, %2;" : "=r"(r) : "r"(addr), "r"(rank));
    return r;
}
__device__ __forceinline__ void st_cluster_f4(uint32_t addr, float4 v) {
    asm volatile("st.shared::cluster.v4.f32 [%0], {%1,%2,%3,%4};"
                 :: "r"(addr), "f"(v.x), "f"(v.y), "f"(v.z), "f"(v.w) : "memory");
}
__device__ __forceinline__ void cluster_sync_() {
    asm volatile("barrier.cluster.arrive.aligned;" ::: "memory");
    asm volatile("barrier.cluster.wait.aligned;" ::: "memory");
}
__device__ __forceinline__ float sigf(float x) {
    return __fdividef(1.f, 1.f + __expf(-x));
}
__device__ __forceinline__ float tanhfast(float x) {
    float a = fabsf(x);
    float e = __expf(2.f * a);
    float r = 1.f - __fdividef(2.f, e + 1.f);
    return copysignf(r, x);
}

// ---------------------------------------------------------------------------
// Kernel 1: projection GEMM (f32x2 microtile).  C[b*1024+t, 0:768] = x @ [Wzr|Wh] + bias
// 128x128 tile, BK=16, 256 threads, 8x8 microtile packed as 8x(4 f32x2 pairs).
// ---------------------------------------------------------------------------
__global__ __launch_bounds__(256, 2) void proj_gemm(
    const float* __restrict__ x,
    const float* __restrict__ Wzr,
    const float* __restrict__ Wh,
    const float* __restrict__ bzr,
    const float* __restrict__ bh)
{
    __shared__ float As[128][16];
    __shared__ float Bs[16][128];

    const int tid = threadIdx.x;
    const int tm = tid >> 4;
    const int tn = tid & 15;
    const int Mbase = blockIdx.y * 128;
    const int Nbase = blockIdx.x * 128;

    const bool isZr = (Nbase < 512);
    const float* __restrict__ W = isZr ? Wzr : Wh;
    const int ldw  = isZr ? 512 : 256;
    const int wcol = isZr ? Nbase : (Nbase - 512);

    ull acc2[8][4];
    #pragma unroll
    for (int i = 0; i < 8; i++)
        #pragma unroll
        for (int p = 0; p < 4; p++) acc2[i][p] = 0ull;

    const int ra = tid >> 2;
    const int ka = (tid & 3) << 2;
    const int rb = tid >> 5;
    const int nb = (tid & 31) << 2;

    for (int kt = 0; kt < 256; kt += 16) {
        float4 a0 = *(const float4*)&x[(size_t)(Mbase + ra)      * 256 + kt + ka];
        float4 a1 = *(const float4*)&x[(size_t)(Mbase + ra + 64) * 256 + kt + ka];
        float4 w0 = *(const float4*)&W[(size_t)(kt + rb)     * ldw + wcol + nb];
        float4 w1 = *(const float4*)&W[(size_t)(kt + rb + 8) * ldw + wcol + nb];
        __syncthreads();
        *(float4*)&As[ra][ka]      = a0;
        *(float4*)&As[ra + 64][ka] = a1;
        *(float4*)&Bs[rb][nb]      = w0;
        *(float4*)&Bs[rb + 8][nb]  = w1;
        __syncthreads();
        #pragma unroll
        for (int kk = 0; kk < 16; kk++) {
            ulonglong2 b01 = *(const ulonglong2*)&Bs[kk][tn * 8];
            ulonglong2 b23 = *(const ulonglong2*)&Bs[kk][tn * 8 + 4];
            #pragma unroll
            for (int i = 0; i < 8; i++) {
                ull ad = dup2f(As[tm * 8 + i][kk]);
                ffma2(acc2[i][0], ad, b01.x);
                ffma2(acc2[i][1], ad, b01.y);
                ffma2(acc2[i][2], ad, b23.x);
                ffma2(acc2[i][3], ad, b23.y);
            }
        }
    }

    float bias[8];
    #pragma unroll
    for (int jj = 0; jj < 8; jj++) {
        int c = Nbase + tn * 8 + jj;
        bias[jj] = (c < 512) ? bzr[c] : bh[c - 512];
    }

    #pragma unroll
    for (int i = 0; i < 8; i++) {
        int r = Mbase + tm * 8 + i;   // r = b*1024 + t
        int b = r >> 10;
        int t = r & 1023;
        float* dst = &g_xzh[(size_t)((t << 7) + b) * 768 + Nbase + tn * 8];
        float c[8];
        #pragma unroll
        for (int p = 0; p < 4; p++) unpack2(acc2[i][p], c[2 * p], c[2 * p + 1]);
        float4 v0, v1;
        v0.x = c[0] + bias[0]; v0.y = c[1] + bias[1];
        v0.z = c[2] + bias[2]; v0.w = c[3] + bias[3];
        v1.x = c[4] + bias[4]; v1.y = c[5] + bias[5];
        v1.z = c[6] + bias[6]; v1.w = c[7] + bias[7];
        *(float4*)dst       = v0;
        *(float4*)(dst + 4) = v1;
    }
}

// ---------------------------------------------------------------------------
// Kernel 2: cluster-resident GRU recurrence.
// 32 clusters x 4 CTAs x 256 threads. Cluster owns 4 batch rows.
// CTA c (rank) holds Uzr cols [128c,128c+128) and Uh cols [64c,64c+64) in SMEM.
// Per step: phase1 (z slice), DSMEM exchange of Z/R*h, phase2 (S slice),
// DSMEM broadcast of h_new. Weights never leave SMEM after the prologue.
// ---------------------------------------------------------------------------
#define SMEM_BYTES 222208
// layout (bytes):
//   wzr4:   0      float4[256*32]  (128 KB)   slice of U_zr, k-major
//   wh2:  131072   float2[256*32]  ( 64 KB)   slice of U_h,  k-major
//   red4: 196608   float4[8*128]   ( 16 KB)   per-warp partials (swizzled)
//   h4:   212992   float4[256]     (  4 KB)   h, rows 0..3 packed per col
//   rh4:  217088   float4[256]     (  4 KB)   R*h
//   z4s:  221184   float4[64]      (  1 KB)   Z slice for this CTA's S cols

extern "C" __global__ void __launch_bounds__(256, 1) __cluster_dims__(4, 1, 1)
gru_recur_cluster(const float* __restrict__ Uzr,
                  const float* __restrict__ Uh,
                  float* __restrict__ out)
{
    extern __shared__ char smem_raw[];
    float4* wzr4 = (float4*)(smem_raw);
    float2* wh2  = (float2*)(smem_raw + 131072);
    float4* red4 = (float4*)(smem_raw + 196608);
    float4* h4   = (float4*)(smem_raw + 212992);
    float4* rh4  = (float4*)(smem_raw + 217088);
    float4* z4s  = (float4*)(smem_raw + 221184);

    const int tid  = threadIdx.x;
    const int wid  = tid >> 5;
    const int lane = tid & 31;
    const uint32_t crank = blockIdx.x & 3;       // == cluster cta rank (cluster dims 4x1x1)
    const int cl = blockIdx.x >> 2;              // cluster index
    const int r0 = cl * 4;                       // first batch row of this cluster

    // ---- prologue: load weight slices, zero h ----
    {
        const float4* Uzr4g = (const float4*)Uzr;   // [256][128] float4 view
        for (int idx = tid; idx < 256 * 32; idx += 256)
            wzr4[idx] = Uzr4g[(idx >> 5) * 128 + crank * 32 + (idx & 31)];
        const float2* Uh2g = (const float2*)Uh;     // [256][128] float2 view
        for (int idx = tid; idx < 256 * 32; idx += 256)
            wh2[idx] = Uh2g[(idx >> 5) * 128 + crank * 32 + (idx & 31)];
    }
    h4[tid] = make_float4(0.f, 0.f, 0.f, 0.f);
    __syncthreads();
    cluster_sync_();

    // DSMEM addresses of peers' buffers
    uint32_t h_base = smem_u32(h4), rh_base = smem_u32(rh4), z_base = smem_u32(z4s);
    uint32_t h_r[4], rh_r[4], z_r[4];
    #pragma unroll
    for (uint32_t r = 0; r < 4; r++) {
        h_r[r]  = mapa_rank(h_base, r);
        rh_r[r] = mapa_rank(rh_base, r);
        z_r[r]  = mapa_rank(z_base, r);
    }

    const ull* h_u2  = (const ull*)h4;
    const ull* rh_u2 = (const ull*)rh4;

    for (int t = 0; t < 1024; t++) {
        // ---- prefetch this step's xz / xh slices (DRAM; consumed ~1K cyc later) ----
        const float* base = g_xzh + (size_t)((t << 7) + r0) * 768;
        float xz0 = 0.f, xz1 = 0.f, xz2 = 0.f, xz3 = 0.f;
        float xh0 = 0.f, xh1 = 0.f, xh2 = 0.f, xh3 = 0.f;
        if (tid < 128) {
            int col = crank * 128 + tid;
            xz0 = base[col]; xz1 = base[768 + col];
            xz2 = base[1536 + col]; xz3 = base[2304 + col];
        }
        if (tid < 64) {
            int col = 512 + crank * 64 + tid;
            xh0 = base[col]; xh1 = base[768 + col];
            xh2 = base[1536 + col]; xh3 = base[2304 + col];
        }

        // ---- phase 1: partial z[4 rows][128 local cols], warp wid owns k in [32w,32w+32) ----
        ull a01[4] = {0, 0, 0, 0}, a23[4] = {0, 0, 0, 0};
        {
            const float4* wp = wzr4 + wid * 32 * 32 + lane;
            const ull*    hp = h_u2 + wid * 64;
            #pragma unroll 4
            for (int kk = 0; kk < 32; kk++) {
                float4 w = wp[kk * 32];                         // cols 4l..4l+3
                ulonglong2 hv = *(const ulonglong2*)&hp[2 * kk]; // rowpairs (0,1),(2,3)
                ull w0 = dup2f(w.x), w1 = dup2f(w.y), w2 = dup2f(w.z), w3 = dup2f(w.w);
                ffma2(a01[0], w0, hv.x); ffma2(a23[0], w0, hv.y);
                ffma2(a01[1], w1, hv.x); ffma2(a23[1], w1, hv.y);
                ffma2(a01[2], w2, hv.x); ffma2(a23[2], w2, hv.y);
                ffma2(a01[3], w3, hv.x); ffma2(a23[3], w3, hv.y);
            }
        }
        #pragma unroll
        for (int i = 0; i < 4; i++) {
            int col = 4 * lane + i;
            int sc = col ^ ((col >> 2) & 7);                    // conflict-free swizzle
            ulonglong2 v; v.x = a01[i]; v.y = a23[i];
            *(ulonglong2*)&red4[wid * 128 + sc] = v;
        }
        __syncthreads();

        // ---- reduce1 + gates + DSMEM routing (threads 0..127, col = tid) ----
        if (tid < 128) {
            int sc = tid ^ ((tid >> 2) & 7);
            float4 s = red4[sc];
            #pragma unroll
            for (int w = 1; w < 8; w++) {
                float4 p = red4[w * 128 + sc];
                s.x += p.x; s.y += p.y; s.z += p.z; s.w += p.w;
            }
            s.x += xz0; s.y += xz1; s.z += xz2; s.w += xz3;
            float4 g;
            g.x = sigf(s.x); g.y = sigf(s.y); g.z = sigf(s.z); g.w = sigf(s.w);
            if (crank < 2) {
                // Z slice: route to the CTA that owns these S columns
                uint32_t dest = 2 * crank + (tid >> 6);
                st_cluster_f4(z_r[dest] + (uint32_t)(tid & 63) * 16, g);
            } else {
                // R slice: broadcast R*h to all 4 CTAs
                int gcol = (crank - 2) * 128 + tid;             // hidden col
                float4 hv = h4[gcol];
                float4 rh; rh.x = g.x * hv.x; rh.y = g.y * hv.y;
                rh.z = g.z * hv.z; rh.w = g.w * hv.w;
                #pragma unroll
                for (uint32_t r = 0; r < 4; r++)
                    st_cluster_f4(rh_r[r] + (uint32_t)gcol * 16, rh);
            }
        }
        cluster_sync_();

        // ---- phase 2: partial S[4 rows][64 local cols] ----
        ull b01[2] = {0, 0}, b23[2] = {0, 0};
        {
            const float2* wp2 = wh2 + wid * 32 * 32 + lane;
            const ull*    rp  = rh_u2 + wid * 64;
            #pragma unroll 4
            for (int kk = 0; kk < 32; kk++) {
                float2 w = wp2[kk * 32];                        // cols 2l..2l+1
                ulonglong2 rv = *(const ulonglong2*)&rp[2 * kk];
                ull w0 = dup2f(w.x), w1 = dup2f(w.y);
                ffma2(b01[0], w0, rv.x); ffma2(b23[0], w0, rv.y);
                ffma2(b01[1], w1, rv.x); ffma2(b23[1], w1, rv.y);
            }
        }
        #pragma unroll
        for (int i = 0; i < 2; i++) {
            int col = 2 * lane + i;
            int sc = col ^ ((col >> 1) & 7);
            ulonglong2 v; v.x = b01[i]; v.y = b23[i];
            *(ulonglong2*)&red4[wid * 64 + sc] = v;
        }
        __syncthreads();

        // ---- reduce2 + combine + h broadcast (threads 0..63, local col = tid) ----
        if (tid < 64) {
            int sc = tid ^ ((tid >> 1) & 7);
            float4 s = red4[sc];
            #pragma unroll
            for (int w = 1; w < 8; w++) {
                float4 p = red4[w * 64 + sc];
                s.x += p.x; s.y += p.y; s.z += p.z; s.w += p.w;
            }
            float4 S;
            S.x = tanhfast(s.x + xh0); S.y = tanhfast(s.y + xh1);
            S.z = tanhfast(s.z + xh2); S.w = tanhfast(s.w + xh3);
            float4 Z = z4s[tid];
            int gcol = crank * 64 + tid;                        // hidden col
            float4 hv = h4[gcol];
            float4 hn;
            hn.x = fmaf(Z.x, S.x - hv.x, hv.x);
            hn.y = fmaf(Z.y, S.y - hv.y, hv.y);
            hn.z = fmaf(Z.z, S.z - hv.z, hv.z);
            hn.w = fmaf(Z.w, S.w - hv.w, hv.w);
            #pragma unroll
            for (uint32_t r = 0; r < 4; r++)
                st_cluster_f4(h_r[r] + (uint32_t)gcol * 16, hn);
        }
        cluster_sync_();
    }

    // ---- epilogue: rank 0 writes the 4 rows ----
    if (crank == 0) {
        float4 hv = h4[tid];
        out[(r0 + 0) * 256 + tid] = hv.x;
        out[(r0 + 1) * 256 + tid] = hv.y;
        out[(r0 + 2) * 256 + tid] = hv.z;
        out[(r0 + 3) * 256 + tid] = hv.w;
    }
}

// ---------------------------------------------------------------------------
extern "C" void kernel_launch(void* const* d_in, const int* in_sizes, int n_in,
                              void* d_out, int out_size)
{
    (void)in_sizes; (void)n_in; (void)out_size;
    const float* x   = (const float*)d_in[0];
    const float* Wzr = (const float*)d_in[1];
    const float* Uzr = (const float*)d_in[2];
    const float* bzr = (const float*)d_in[3];
    const float* Wh  = (const float*)d_in[4];
    const float* Uh  = (const float*)d_in[5];
    const float* bh  = (const float*)d_in[6];

    dim3 ggrid(6, 1024);
    proj_gemm<<<ggrid, 256>>>(x, Wzr, Wh, bzr, bh);

    cudaFuncSetAttribute(gru_recur_cluster,
                         cudaFuncAttributeMaxDynamicSharedMemorySize, SMEM_BYTES);
    gru_recur_cluster<<<128, 256, SMEM_BYTES>>>(Uzr, Uh, (float*)d_out);
}